// round 16
// baseline (speedup 1.0000x reference)
#include <cuda_runtime.h>
#include <cuda_fp16.h>
#include <stdint.h>

// Problem constants
#define BATCH 1024
#define NA    10
#define NE    11
#define AF    32
#define EF    28
#define HYP   64
#define OUTD  256

// Concatenated-K layout:
//   [0,2048) M_ally  [2048,2080) xsum_ally  [2080,3872) M_enemy
//   [3872,3900) xsum_enemy  [3900,3904) pad
#define KA      (HYP*AF)
#define OFF_FA  KA
#define OFF_ME  (KA+AF)
#define KE      (HYP*EF)
#define OFF_FE  (OFF_ME+KE)
#define KTOT    (OFF_FE+EF)
#define KP      3904
#define SPLIT   12
#define BK      64
#define NST     (KP/BK)        // 61 stages
#define NPACK   ((KP/64)*4)    // 244 pack tiles

// fp16 operands (combined rounding ~3e-4 rel err, validated R13)
__device__ __align__(16) __half g_Ua[BATCH * KP];     // A [m][k]
__device__ __align__(16) __half g_Wt[OUTD * KP];      // B^T [n][k]
__device__ float g_P[SPLIT * BATCH * OUTD];           // split-K partials
__device__ int   g_cnt[32];                           // per-tile counters (zero-init)

// ---------------------------------------------------------------------------
// helpers
// ---------------------------------------------------------------------------
__device__ __forceinline__ uint32_t smem_u32(const void* p) {
    uint32_t a;
    asm("{ .reg .u64 t; cvta.to.shared.u64 t, %1; cvt.u32.u64 %0, t; }" : "=r"(a) : "l"(p));
    return a;
}
__device__ __forceinline__ void cp16(uint32_t dst, const void* src) {
    asm volatile("cp.async.cg.shared.global [%0], [%1], 16;" :: "r"(dst), "l"(src));
}
#define CP_COMMIT() asm volatile("cp.async.commit_group;" ::: "memory")
#define CP_WAIT(N)  asm volatile("cp.async.wait_group %0;" :: "n"(N) : "memory")

__device__ __forceinline__ void ldsm4(uint32_t& r0, uint32_t& r1, uint32_t& r2,
                                      uint32_t& r3, uint32_t addr) {
    asm volatile("ldmatrix.sync.aligned.m8n8.x4.shared.b16 {%0,%1,%2,%3}, [%4];"
                 : "=r"(r0), "=r"(r1), "=r"(r2), "=r"(r3) : "r"(addr));
}
__device__ __forceinline__ void mma_f16(float* c, const uint32_t* a, const uint32_t* b) {
    asm volatile(
        "mma.sync.aligned.m16n8k16.row.col.f32.f16.f16.f32 "
        "{%0,%1,%2,%3},{%4,%5,%6,%7},{%8,%9},{%0,%1,%2,%3};"
        : "+f"(c[0]), "+f"(c[1]), "+f"(c[2]), "+f"(c[3])
        : "r"(a[0]), "r"(a[1]), "r"(a[2]), "r"(a[3]), "r"(b[0]), "r"(b[1]));
}

// register-only fp16x2 pack: d = {hi:b, lo:a}  (one F2FP instruction)
__device__ __forceinline__ uint32_t f2h2(float lo, float hi) {
    uint32_t r;
    asm("cvt.rn.f16x2.f32 %0, %1, %2;" : "=r"(r) : "f"(hi), "f"(lo));
    return r;
}
__device__ __forceinline__ void emit8h(__half* p, size_t idx, const float* v) {
    uint4 val;
    val.x = f2h2(v[0], v[1]);
    val.y = f2h2(v[2], v[3]);
    val.z = f2h2(v[4], v[5]);
    val.w = f2h2(v[6], v[7]);
    *(uint4*)(p + idx) = val;
}
__device__ __forceinline__ void emit4h(__half* p, size_t idx, const float* v) {
    uint2 val;
    val.x = f2h2(v[0], v[1]);
    val.y = f2h2(v[2], v[3]);
    *(uint2*)(p + idx) = val;
}

// ---------------------------------------------------------------------------
// Kernel 0: no-op (launch-slot alignment so ncu -s 5 lands on build_u)
// ---------------------------------------------------------------------------
__global__ void knop() {}

// ---------------------------------------------------------------------------
// Kernel 1 "build_u": one block per batch element. Weights staged transposed
// ([k][f], 36-float padded rows) so hidden-layer reads are LDS.128.
// ---------------------------------------------------------------------------
#define WSTR 36

struct BuildSmem {
    float wa1t[HYP * WSTR];   // [k][f] f<32
    float we1t[HYP * WSTR];   // [k][f] f<28
    float fa[NA][AF];
    float fe[NE][EF];
    float ha[NA][HYP];
    float he[NE][HYP];
};

__global__ __launch_bounds__(256) void build_u(
    const float* __restrict__ fa, const float* __restrict__ fe,
    const float* __restrict__ wa1, const float* __restrict__ ba1,
    const float* __restrict__ we1, const float* __restrict__ be1) {

    __shared__ BuildSmem sm;
    const int t = threadIdx.x;
    const int b = blockIdx.x;
    const size_t rb = (size_t)b * KP;

    // stage weights transposed (float4 loads, scalar scatter stores)
    for (int i4 = t; i4 < (AF * HYP) / 4; i4 += 256) {
        float4 w = ((const float4*)wa1)[i4];
        int base = i4 * 4;
        int f = base >> 6, k = base & 63;
        sm.wa1t[(k + 0) * WSTR + f] = w.x;
        sm.wa1t[(k + 1) * WSTR + f] = w.y;
        sm.wa1t[(k + 2) * WSTR + f] = w.z;
        sm.wa1t[(k + 3) * WSTR + f] = w.w;
    }
    for (int i4 = t; i4 < (EF * HYP) / 4; i4 += 256) {
        float4 w = ((const float4*)we1)[i4];
        int base = i4 * 4;
        int f = base >> 6, k = base & 63;
        sm.we1t[(k + 0) * WSTR + f] = w.x;
        sm.we1t[(k + 1) * WSTR + f] = w.y;
        sm.we1t[(k + 2) * WSTR + f] = w.z;
        sm.we1t[(k + 3) * WSTR + f] = w.w;
    }
    for (int i = t; i < NA * AF; i += 256) sm.fa[i / AF][i % AF] = fa[b * NA * AF + i];
    for (int i = t; i < NE * EF; i += 256) sm.fe[i / EF][i % EF] = fe[b * NE * EF + i];
    __syncthreads();

    // hidden layers — vectorized LDS.128 on both operands
    for (int i = t; i < NA * HYP; i += 256) {
        int n = i / HYP, k = i % HYP;
        const float4* wr = (const float4*)&sm.wa1t[k * WSTR];
        const float4* xr = (const float4*)&sm.fa[n][0];
        float s = ba1[k];
        #pragma unroll
        for (int q = 0; q < 8; q++) {
            float4 w = wr[q], x = xr[q];
            s += x.x * w.x + x.y * w.y + x.z * w.z + x.w * w.w;
        }
        sm.ha[n][k] = fmaxf(s, 0.0f);
    }
    for (int i = t; i < NE * HYP; i += 256) {
        int n = i / HYP, k = i % HYP;
        const float4* wr = (const float4*)&sm.we1t[k * WSTR];
        const float4* xr = (const float4*)&sm.fe[n][0];
        float s = be1[k];
        #pragma unroll
        for (int q = 0; q < 7; q++) {
            float4 w = wr[q], x = xr[q];
            s += x.x * w.x + x.y * w.y + x.z * w.z + x.w * w.w;
        }
        sm.he[n][k] = fmaxf(s, 0.0f);
    }
    __syncthreads();

    // ally outer products: 256 items = k(64) x f8(4), 8-wide
    {
        int k = t >> 2, f8 = (t & 3) * 8;
        float s[8] = {};
        #pragma unroll
        for (int n = 0; n < NA; n++) {
            float h = sm.ha[n][k];
            #pragma unroll
            for (int j = 0; j < 8; j++) s[j] += h * sm.fa[n][f8 + j];
        }
        emit8h(g_Ua, rb + k * AF + f8, s);
    }
    // enemy outer products: 448 items = k(64) x f4(7), 4-wide
    for (int it = t; it < 448; it += 256) {
        int k = it / 7, f4 = (it - k * 7) * 4;
        float s[4] = {};
        #pragma unroll
        for (int n = 0; n < NE; n++) {
            float h = sm.he[n][k];
            #pragma unroll
            for (int j = 0; j < 4; j++) s[j] += h * sm.fe[n][f4 + j];
        }
        emit4h(g_Ua, rb + OFF_ME + k * EF + f4, s);
    }
    if (t < 4) {
        int f8 = t * 8;
        float s[8] = {};
        #pragma unroll
        for (int n = 0; n < NA; n++)
            #pragma unroll
            for (int j = 0; j < 8; j++) s[j] += sm.fa[n][f8 + j];
        emit8h(g_Ua, rb + OFF_FA + f8, s);
    } else if (t >= 8 && t < 15) {
        int f4 = (t - 8) * 4;
        float s[4] = {};
        #pragma unroll
        for (int n = 0; n < NE; n++)
            #pragma unroll
            for (int j = 0; j < 4; j++) s[j] += sm.fe[n][f4 + j];
        emit4h(g_Ua, rb + OFF_FE + f4, s);
    } else if (t == 16) {
        float s[4] = {};
        emit4h(g_Ua, rb + KTOT, s);
    }
}

// ---------------------------------------------------------------------------
// Kernel 2 "pack": transpose + convert combined weight into Wt[n][k] fp16.
// ---------------------------------------------------------------------------
__global__ __launch_bounds__(256) void pack(
    const float* __restrict__ wa2, const float* __restrict__ ba2,
    const float* __restrict__ we2, const float* __restrict__ be2) {

    __shared__ float s[64][65];
    const int t = threadIdx.x;
    const int k0 = (blockIdx.x >> 2) * 64;
    const int n0 = (blockIdx.x & 3) * 64;

    for (int i = t; i < 64 * 64; i += 256) {
        int kl = i >> 6, nl = i & 63;
        int r = k0 + kl, n = n0 + nl;
        float v;
        if (r < KA)            v = wa2[(size_t)r * OUTD + n];
        else if (r < OFF_ME)   v = ba2[(size_t)(r - KA) * OUTD + n];
        else if (r < OFF_FE)   v = we2[(size_t)(r - OFF_ME) * OUTD + n];
        else if (r < KTOT)     v = be2[(size_t)(r - OFF_FE) * OUTD + n];
        else                   v = 0.0f;
        s[kl][nl] = v;
    }
    __syncthreads();
    for (int i = t; i < 512; i += 256) {
        int nl = i >> 3, kl8 = (i & 7) * 8;
        float v[8];
        #pragma unroll
        for (int j = 0; j < 8; j++) v[j] = s[kl8 + j][nl];
        emit8h(g_Wt, (size_t)(n0 + nl) * KP + k0 + kl8, v);
    }
}

// ---------------------------------------------------------------------------
// Kernel 3: single-pass fp16 HMMA GEMM. BM=128, BN=64, BK=64, 2-stage
// cp.async, 256 threads / 8 warps, warp tile 32x32 (2mt x 4nt).
// grid (8, 4, SPLIT=12) = 384 CTAs. Fused last-CTA split-K reduce.
// ---------------------------------------------------------------------------
#define ASTRIDE 72                       // fp16 elems per row (144 B, ldsm-clean)
#define ASZ1    (128 * ASTRIDE * 2)      // 18432 B per A stage
#define BSZ1    (64 * ASTRIDE * 2)       // 9216 B per B stage
#define OFF_A   0
#define OFF_B   (2 * ASZ1)               // 36864
#define SMEM_DYN (2 * ASZ1 + 2 * BSZ1)   // 55296

__global__ void __launch_bounds__(256, 3) gemm_mma(float* __restrict__ out) {
    extern __shared__ char dsm[];
    __shared__ int s_old;
    const uint32_t sb = smem_u32(dsm);

    const int t    = threadIdx.x;
    const int lane = t & 31;
    const int wid  = t >> 5;
    const int wm   = (wid & 3) * 32;
    const int wn   = (wid >> 2) * 32;
    const int m0   = blockIdx.x * 128;
    const int n0   = blockIdx.y * 64;
    const int z    = blockIdx.z;
    const int s0   = (NST * z) / SPLIT;
    const int s1   = (NST * (z + 1)) / SPLIT;

    const int a_row = lane & 15;
    const int a_k8  = ((lane >> 4) & 1) * 8;
    const int b_row = (lane & 7) + ((lane >> 4) & 1) * 8;
    const int b_k8  = (lane & 8);

    float acc[2][4][4];
    #pragma unroll
    for (int i = 0; i < 2; i++)
        #pragma unroll
        for (int j = 0; j < 4; j++)
            #pragma unroll
            for (int q = 0; q < 4; q++) acc[i][j][q] = 0.0f;

    auto issue = [&](int s, int buf) {
        const int k0 = s * BK;
        #pragma unroll
        for (int q = 0; q < 4; q++) {
            int idx = t + q * 256;               // [0,1024): A 128 rows x 8 chunks
            int m = idx >> 3, kc = idx & 7;
            uint32_t doff = (uint32_t)(m * ASTRIDE + kc * 8) * 2;
            cp16(sb + OFF_A + buf * ASZ1 + doff,
                 g_Ua + (size_t)(m0 + m) * KP + k0 + kc * 8);
        }
        #pragma unroll
        for (int q = 0; q < 2; q++) {
            int idx = t + q * 256;               // [0,512): B 64 rows x 8 chunks
            int n = idx >> 3, kc = idx & 7;
            uint32_t doff = (uint32_t)(n * ASTRIDE + kc * 8) * 2;
            cp16(sb + OFF_B + buf * BSZ1 + doff,
                 g_Wt + (size_t)(n0 + n) * KP + k0 + kc * 8);
        }
    };

    issue(s0, 0);
    CP_COMMIT();
    if (s0 + 1 < s1) issue(s0 + 1, 1);
    CP_COMMIT();

    int buf = 0;
    for (int s = s0; s < s1; s++) {
        CP_WAIT(1);            // stage s landed
        __syncthreads();

        const uint32_t baseA = sb + OFF_A + buf * ASZ1;
        const uint32_t baseB = sb + OFF_B + buf * BSZ1;

        #pragma unroll
        for (int kk = 0; kk < 4; kk++) {
            const int kcol = kk * 16;
            uint32_t A[2][4], B[4][2];
            #pragma unroll
            for (int p = 0; p < 2; p++) {
                uint32_t off = (uint32_t)((wn + p * 16 + b_row) * ASTRIDE + kcol + b_k8) * 2;
                ldsm4(B[2 * p][0], B[2 * p][1], B[2 * p + 1][0], B[2 * p + 1][1], baseB + off);
            }
            #pragma unroll
            for (int mt = 0; mt < 2; mt++) {
                uint32_t off = (uint32_t)((wm + mt * 16 + a_row) * ASTRIDE + kcol + a_k8) * 2;
                ldsm4(A[mt][0], A[mt][1], A[mt][2], A[mt][3], baseA + off);
            }
            #pragma unroll
            for (int mt = 0; mt < 2; mt++)
                #pragma unroll
                for (int nt = 0; nt < 4; nt++)
                    mma_f16(acc[mt][nt], A[mt], B[nt]);
        }
        __syncthreads();       // compute(s) done: buf reusable

        if (s + 2 < s1) issue(s + 2, buf);
        CP_COMMIT();           // unconditional: uniform group counting
        buf ^= 1;
    }

    // write this CTA's split-K partial
    float* P = g_P + (size_t)z * (BATCH * OUTD);
    const int gr  = lane >> 2;
    const int tc2 = (lane & 3) * 2;
    #pragma unroll
    for (int mt = 0; mt < 2; mt++) {
        #pragma unroll
        for (int nt = 0; nt < 4; nt++) {
            int row = m0 + wm + mt * 16 + gr;
            int col = n0 + wn + nt * 8 + tc2;
            *(float2*)(P + (size_t)row * OUTD + col) =
                make_float2(acc[mt][nt][0], acc[mt][nt][1]);
            *(float2*)(P + (size_t)(row + 8) * OUTD + col) =
                make_float2(acc[mt][nt][2], acc[mt][nt][3]);
        }
    }

    // ---- fused split-K reduction: last CTA per (m,n) tile sums partials ----
    __threadfence();
    __syncthreads();
    const int tile = blockIdx.x * 4 + blockIdx.y;
    if (t == 0) s_old = atomicAdd(&g_cnt[tile], 1);
    __syncthreads();
    if (s_old == SPLIT - 1) {
        __threadfence();   // acquire: see peers' partials
        for (int i = t; i < 128 * 64 / 4; i += 256) {
            int r = i >> 4;
            int c = (i & 15) * 4;
            size_t off = (size_t)(m0 + r) * OUTD + n0 + c;
            float4 s = *(const float4*)(g_P + off);
            #pragma unroll
            for (int zz = 1; zz < SPLIT; zz++) {
                const float4 v = *(const float4*)(g_P + (size_t)zz * (BATCH * OUTD) + off);
                s.x += v.x; s.y += v.y; s.z += v.z; s.w += v.w;
            }
            *(float4*)(out + off) = s;
        }
        __syncthreads();
        if (t == 0) g_cnt[tile] = 0;   // reset for next graph replay
    }
}

// ---------------------------------------------------------------------------
// Inputs: 0 ally 1 enemy 2 wa1 3 ba1 4 wa2 5 ba2 6 we1 7 be1 8 we2 9 be2
// Launch order [nop, build_u, pack, gemm]: ncu -s 5 lands on build_u.
// ---------------------------------------------------------------------------
extern "C" void kernel_launch(void* const* d_in, const int* in_sizes, int n_in,
                              void* d_out, int out_size) {
    const float* fa  = (const float*)d_in[0];
    const float* fe  = (const float*)d_in[1];
    const float* wa1 = (const float*)d_in[2];
    const float* ba1 = (const float*)d_in[3];
    const float* wa2 = (const float*)d_in[4];
    const float* ba2 = (const float*)d_in[5];
    const float* we1 = (const float*)d_in[6];
    const float* be1 = (const float*)d_in[7];
    const float* we2 = (const float*)d_in[8];
    const float* be2 = (const float*)d_in[9];
    float* out = (float*)d_out;

    cudaFuncSetAttribute(gemm_mma, cudaFuncAttributeMaxDynamicSharedMemorySize, SMEM_DYN);

    knop<<<1, 32>>>();
    build_u<<<BATCH, 256>>>(fa, fe, wa1, ba1, we1, be1);
    pack<<<NPACK, 256>>>(wa2, ba2, we2, be2);
    gemm_mma<<<dim3(BATCH / 128, OUTD / 64, SPLIT), 256, SMEM_DYN>>>(out);
}

// round 17
// speedup vs baseline: 1.0898x; 1.0898x over previous
#include <cuda_runtime.h>
#include <cuda_fp16.h>
#include <stdint.h>

// Problem constants
#define BATCH 1024
#define NA    10
#define NE    11
#define AF    32
#define EF    28
#define HYP   64
#define OUTD  256

// Concatenated-K layout:
//   [0,2048) M_ally  [2048,2080) xsum_ally  [2080,3872) M_enemy
//   [3872,3900) xsum_enemy  [3900,3904) pad
#define KA      (HYP*AF)
#define OFF_FA  KA
#define OFF_ME  (KA+AF)
#define KE      (HYP*EF)
#define OFF_FE  (OFF_ME+KE)
#define KTOT    (OFF_FE+EF)
#define KP      3904
#define SPLIT   12
#define BK      64
#define NST     (KP/BK)        // 61 stages
#define NPACK   ((KP/64)*4)    // 244 pack tiles

// fp16 operands (combined rounding ~2.9e-4 rel err, validated R13/R14)
__device__ __align__(16) __half g_Ua[BATCH * KP];     // A [m][k]
__device__ __align__(16) __half g_Wt[OUTD * KP];      // B^T [n][k]
__device__ float g_P[SPLIT * BATCH * OUTD];           // split-K partials
__device__ int   g_cnt[32];                           // per-tile counters (zero-init)

// ---------------------------------------------------------------------------
// helpers
// ---------------------------------------------------------------------------
__device__ __forceinline__ uint32_t smem_u32(const void* p) {
    uint32_t a;
    asm("{ .reg .u64 t; cvta.to.shared.u64 t, %1; cvt.u32.u64 %0, t; }" : "=r"(a) : "l"(p));
    return a;
}
__device__ __forceinline__ void cp16(uint32_t dst, const void* src) {
    asm volatile("cp.async.cg.shared.global [%0], [%1], 16;" :: "r"(dst), "l"(src));
}
#define CP_COMMIT() asm volatile("cp.async.commit_group;" ::: "memory")
#define CP_WAIT(N)  asm volatile("cp.async.wait_group %0;" :: "n"(N) : "memory")

__device__ __forceinline__ void ldsm4(uint32_t& r0, uint32_t& r1, uint32_t& r2,
                                      uint32_t& r3, uint32_t addr) {
    asm volatile("ldmatrix.sync.aligned.m8n8.x4.shared.b16 {%0,%1,%2,%3}, [%4];"
                 : "=r"(r0), "=r"(r1), "=r"(r2), "=r"(r3) : "r"(addr));
}
__device__ __forceinline__ void mma_f16(float* c, const uint32_t* a, const uint32_t* b) {
    asm volatile(
        "mma.sync.aligned.m16n8k16.row.col.f32.f16.f16.f32 "
        "{%0,%1,%2,%3},{%4,%5,%6,%7},{%8,%9},{%0,%1,%2,%3};"
        : "+f"(c[0]), "+f"(c[1]), "+f"(c[2]), "+f"(c[3])
        : "r"(a[0]), "r"(a[1]), "r"(a[2]), "r"(a[3]), "r"(b[0]), "r"(b[1]));
}

// register-only fp16x2 pack (one F2FP instruction)
__device__ __forceinline__ uint32_t f2h2(float lo, float hi) {
    uint32_t r;
    asm("cvt.rn.f16x2.f32 %0, %1, %2;" : "=r"(r) : "f"(hi), "f"(lo));
    return r;
}
__device__ __forceinline__ void emit8h(__half* p, size_t idx, const float* v) {
    uint4 val;
    val.x = f2h2(v[0], v[1]);
    val.y = f2h2(v[2], v[3]);
    val.z = f2h2(v[4], v[5]);
    val.w = f2h2(v[6], v[7]);
    *(uint4*)(p + idx) = val;
}
__device__ __forceinline__ void emit4h(__half* p, size_t idx, const float* v) {
    uint2 val;
    val.x = f2h2(v[0], v[1]);
    val.y = f2h2(v[2], v[3]);
    *(uint2*)(p + idx) = val;
}

// ---------------------------------------------------------------------------
// Kernel 1 "prep": blocks [0,BATCH) build U; [BATCH,BATCH+NPACK) pack Wt.
// Weights staged transposed ([k][f], 36-float rows) -> hidden reads LDS.128;
// outer-product feature reads vectorized (LDS.128).
// ---------------------------------------------------------------------------
#define WSTR 36

struct PrepSmem {
    union {
        float pack_s[64][65];
        struct {
            float wa1t[HYP * WSTR];   // [k][f] f<32
            float we1t[HYP * WSTR];   // [k][f] f<28
            float fa[NA][AF];
            float fe[NE][EF];
            float ha[NA][HYP];
            float he[NE][HYP];
        } b;
    };
};

__global__ __launch_bounds__(256) void prep(
    const float* __restrict__ fa, const float* __restrict__ fe,
    const float* __restrict__ wa1, const float* __restrict__ ba1,
    const float* __restrict__ wa2, const float* __restrict__ ba2,
    const float* __restrict__ we1, const float* __restrict__ be1,
    const float* __restrict__ we2, const float* __restrict__ be2) {

    __shared__ PrepSmem sm;
    const int t = threadIdx.x;

    if (blockIdx.x >= BATCH) {
        // ---- pack: transpose + convert combined weight into Wt[n][k] ----
        const int pb = blockIdx.x - BATCH;
        const int k0 = (pb >> 2) * 64;
        const int n0 = (pb & 3) * 64;

        for (int i = t; i < 64 * 64; i += 256) {
            int kl = i >> 6, nl = i & 63;
            int r = k0 + kl, n = n0 + nl;
            float v;
            if (r < KA)            v = wa2[(size_t)r * OUTD + n];
            else if (r < OFF_ME)   v = ba2[(size_t)(r - KA) * OUTD + n];
            else if (r < OFF_FE)   v = we2[(size_t)(r - OFF_ME) * OUTD + n];
            else if (r < KTOT)     v = be2[(size_t)(r - OFF_FE) * OUTD + n];
            else                   v = 0.0f;
            sm.pack_s[kl][nl] = v;
        }
        __syncthreads();
        for (int i = t; i < 512; i += 256) {
            int nl = i >> 3, kl8 = (i & 7) * 8;
            float v[8];
            #pragma unroll
            for (int j = 0; j < 8; j++) v[j] = sm.pack_s[kl8 + j][nl];
            emit8h(g_Wt, (size_t)(n0 + nl) * KP + k0 + kl8, v);
        }
        return;
    }

    // ---- build U for batch element b ----
    const int b = blockIdx.x;
    const size_t rb = (size_t)b * KP;

    // stage weights transposed (float4 loads, scalar scatter stores)
    for (int i4 = t; i4 < (AF * HYP) / 4; i4 += 256) {
        float4 w = ((const float4*)wa1)[i4];
        int base = i4 * 4;
        int f = base >> 6, k = base & 63;
        sm.b.wa1t[(k + 0) * WSTR + f] = w.x;
        sm.b.wa1t[(k + 1) * WSTR + f] = w.y;
        sm.b.wa1t[(k + 2) * WSTR + f] = w.z;
        sm.b.wa1t[(k + 3) * WSTR + f] = w.w;
    }
    for (int i4 = t; i4 < (EF * HYP) / 4; i4 += 256) {
        float4 w = ((const float4*)we1)[i4];
        int base = i4 * 4;
        int f = base >> 6, k = base & 63;
        sm.b.we1t[(k + 0) * WSTR + f] = w.x;
        sm.b.we1t[(k + 1) * WSTR + f] = w.y;
        sm.b.we1t[(k + 2) * WSTR + f] = w.z;
        sm.b.we1t[(k + 3) * WSTR + f] = w.w;
    }
    for (int i = t; i < NA * AF; i += 256) sm.b.fa[i / AF][i % AF] = fa[b * NA * AF + i];
    for (int i = t; i < NE * EF; i += 256) sm.b.fe[i / EF][i % EF] = fe[b * NE * EF + i];
    __syncthreads();

    // hidden layers — LDS.128 on both operands
    for (int i = t; i < NA * HYP; i += 256) {
        int n = i / HYP, k = i % HYP;
        const float4* wr = (const float4*)&sm.b.wa1t[k * WSTR];
        const float4* xr = (const float4*)&sm.b.fa[n][0];
        float s = ba1[k];
        #pragma unroll
        for (int q = 0; q < 8; q++) {
            float4 w = wr[q], x = xr[q];
            s += x.x * w.x + x.y * w.y + x.z * w.z + x.w * w.w;
        }
        sm.b.ha[n][k] = fmaxf(s, 0.0f);
    }
    for (int i = t; i < NE * HYP; i += 256) {
        int n = i / HYP, k = i % HYP;
        const float4* wr = (const float4*)&sm.b.we1t[k * WSTR];
        const float4* xr = (const float4*)&sm.b.fe[n][0];
        float s = be1[k];
        #pragma unroll
        for (int q = 0; q < 7; q++) {
            float4 w = wr[q], x = xr[q];
            s += x.x * w.x + x.y * w.y + x.z * w.z + x.w * w.w;
        }
        sm.b.he[n][k] = fmaxf(s, 0.0f);
    }
    __syncthreads();

    // ally outer products: 256 items = k(64) x f8(4); vectorized feature reads
    {
        int k = t >> 2, f8 = (t & 3) * 8;
        float s[8] = {};
        #pragma unroll
        for (int n = 0; n < NA; n++) {
            float h = sm.b.ha[n][k];
            float4 x0 = *(const float4*)&sm.b.fa[n][f8];
            float4 x1 = *(const float4*)&sm.b.fa[n][f8 + 4];
            s[0] += h * x0.x; s[1] += h * x0.y; s[2] += h * x0.z; s[3] += h * x0.w;
            s[4] += h * x1.x; s[5] += h * x1.y; s[6] += h * x1.z; s[7] += h * x1.w;
        }
        emit8h(g_Ua, rb + k * AF + f8, s);
    }
    // enemy outer products: 448 items = k(64) x f4(7); vectorized feature reads
    for (int it = t; it < 448; it += 256) {
        int k = it / 7, f4 = (it - k * 7) * 4;
        float s[4] = {};
        #pragma unroll
        for (int n = 0; n < NE; n++) {
            float h = sm.b.he[n][k];
            float4 x = *(const float4*)&sm.b.fe[n][f4];
            s[0] += h * x.x; s[1] += h * x.y; s[2] += h * x.z; s[3] += h * x.w;
        }
        emit4h(g_Ua, rb + OFF_ME + k * EF + f4, s);
    }
    if (t < 4) {
        int f8 = t * 8;
        float s[8] = {};
        #pragma unroll
        for (int n = 0; n < NA; n++) {
            float4 x0 = *(const float4*)&sm.b.fa[n][f8];
            float4 x1 = *(const float4*)&sm.b.fa[n][f8 + 4];
            s[0] += x0.x; s[1] += x0.y; s[2] += x0.z; s[3] += x0.w;
            s[4] += x1.x; s[5] += x1.y; s[6] += x1.z; s[7] += x1.w;
        }
        emit8h(g_Ua, rb + OFF_FA + f8, s);
    } else if (t >= 8 && t < 15) {
        int f4 = (t - 8) * 4;
        float s[4] = {};
        #pragma unroll
        for (int n = 0; n < NE; n++) {
            float4 x = *(const float4*)&sm.b.fe[n][f4];
            s[0] += x.x; s[1] += x.y; s[2] += x.z; s[3] += x.w;
        }
        emit4h(g_Ua, rb + OFF_FE + f4, s);
    } else if (t == 16) {
        float s[4] = {};
        emit4h(g_Ua, rb + KTOT, s);
    }
}

// ---------------------------------------------------------------------------
// Kernel 2: single-pass fp16 HMMA GEMM. BM=128, BN=64, BK=64, 2-stage
// cp.async, 256 threads / 8 warps, warp tile 32x32 (2mt x 4nt).
// grid (8, 4, SPLIT=12) = 384 CTAs. Fused last-CTA split-K reduce.
// ---------------------------------------------------------------------------
#define ASTRIDE 72                       // fp16 elems per row (144 B, ldsm-clean)
#define ASZ1    (128 * ASTRIDE * 2)      // 18432 B per A stage
#define BSZ1    (64 * ASTRIDE * 2)       // 9216 B per B stage
#define OFF_A   0
#define OFF_B   (2 * ASZ1)               // 36864
#define SMEM_DYN (2 * ASZ1 + 2 * BSZ1)   // 55296

__global__ void __launch_bounds__(256, 3) gemm_mma(float* __restrict__ out) {
    extern __shared__ char dsm[];
    __shared__ int s_old;
    const uint32_t sb = smem_u32(dsm);

    const int t    = threadIdx.x;
    const int lane = t & 31;
    const int wid  = t >> 5;
    const int wm   = (wid & 3) * 32;
    const int wn   = (wid >> 2) * 32;
    const int m0   = blockIdx.x * 128;
    const int n0   = blockIdx.y * 64;
    const int z    = blockIdx.z;
    const int s0   = (NST * z) / SPLIT;
    const int s1   = (NST * (z + 1)) / SPLIT;

    const int a_row = lane & 15;
    const int a_k8  = ((lane >> 4) & 1) * 8;
    const int b_row = (lane & 7) + ((lane >> 4) & 1) * 8;
    const int b_k8  = (lane & 8);

    float acc[2][4][4];
    #pragma unroll
    for (int i = 0; i < 2; i++)
        #pragma unroll
        for (int j = 0; j < 4; j++)
            #pragma unroll
            for (int q = 0; q < 4; q++) acc[i][j][q] = 0.0f;

    auto issue = [&](int s, int buf) {
        const int k0 = s * BK;
        #pragma unroll
        for (int q = 0; q < 4; q++) {
            int idx = t + q * 256;               // [0,1024): A 128 rows x 8 chunks
            int m = idx >> 3, kc = idx & 7;
            uint32_t doff = (uint32_t)(m * ASTRIDE + kc * 8) * 2;
            cp16(sb + OFF_A + buf * ASZ1 + doff,
                 g_Ua + (size_t)(m0 + m) * KP + k0 + kc * 8);
        }
        #pragma unroll
        for (int q = 0; q < 2; q++) {
            int idx = t + q * 256;               // [0,512): B 64 rows x 8 chunks
            int n = idx >> 3, kc = idx & 7;
            uint32_t doff = (uint32_t)(n * ASTRIDE + kc * 8) * 2;
            cp16(sb + OFF_B + buf * BSZ1 + doff,
                 g_Wt + (size_t)(n0 + n) * KP + k0 + kc * 8);
        }
    };

    issue(s0, 0);
    CP_COMMIT();
    if (s0 + 1 < s1) issue(s0 + 1, 1);
    CP_COMMIT();

    int buf = 0;
    for (int s = s0; s < s1; s++) {
        CP_WAIT(1);            // stage s landed
        __syncthreads();

        const uint32_t baseA = sb + OFF_A + buf * ASZ1;
        const uint32_t baseB = sb + OFF_B + buf * BSZ1;

        #pragma unroll
        for (int kk = 0; kk < 4; kk++) {
            const int kcol = kk * 16;
            uint32_t A[2][4], B[4][2];
            #pragma unroll
            for (int p = 0; p < 2; p++) {
                uint32_t off = (uint32_t)((wn + p * 16 + b_row) * ASTRIDE + kcol + b_k8) * 2;
                ldsm4(B[2 * p][0], B[2 * p][1], B[2 * p + 1][0], B[2 * p + 1][1], baseB + off);
            }
            #pragma unroll
            for (int mt = 0; mt < 2; mt++) {
                uint32_t off = (uint32_t)((wm + mt * 16 + a_row) * ASTRIDE + kcol + a_k8) * 2;
                ldsm4(A[mt][0], A[mt][1], A[mt][2], A[mt][3], baseA + off);
            }
            #pragma unroll
            for (int mt = 0; mt < 2; mt++)
                #pragma unroll
                for (int nt = 0; nt < 4; nt++)
                    mma_f16(acc[mt][nt], A[mt], B[nt]);
        }
        __syncthreads();       // compute(s) done: buf reusable

        if (s + 2 < s1) issue(s + 2, buf);
        CP_COMMIT();           // unconditional: uniform group counting
        buf ^= 1;
    }

    // write this CTA's split-K partial
    float* P = g_P + (size_t)z * (BATCH * OUTD);
    const int gr  = lane >> 2;
    const int tc2 = (lane & 3) * 2;
    #pragma unroll
    for (int mt = 0; mt < 2; mt++) {
        #pragma unroll
        for (int nt = 0; nt < 4; nt++) {
            int row = m0 + wm + mt * 16 + gr;
            int col = n0 + wn + nt * 8 + tc2;
            *(float2*)(P + (size_t)row * OUTD + col) =
                make_float2(acc[mt][nt][0], acc[mt][nt][1]);
            *(float2*)(P + (size_t)(row + 8) * OUTD + col) =
                make_float2(acc[mt][nt][2], acc[mt][nt][3]);
        }
    }

    // ---- fused split-K reduction: last CTA per (m,n) tile sums partials ----
    __threadfence();
    __syncthreads();
    const int tile = blockIdx.x * 4 + blockIdx.y;
    if (t == 0) s_old = atomicAdd(&g_cnt[tile], 1);
    __syncthreads();
    if (s_old == SPLIT - 1) {
        __threadfence();   // acquire: see peers' partials
        for (int i = t; i < 128 * 64 / 4; i += 256) {
            int r = i >> 4;
            int c = (i & 15) * 4;
            size_t off = (size_t)(m0 + r) * OUTD + n0 + c;
            float4 s = *(const float4*)(g_P + off);
            #pragma unroll
            for (int zz = 1; zz < SPLIT; zz++) {
                const float4 v = *(const float4*)(g_P + (size_t)zz * (BATCH * OUTD) + off);
                s.x += v.x; s.y += v.y; s.z += v.z; s.w += v.w;
            }
            *(float4*)(out + off) = s;
        }
        __syncthreads();
        if (t == 0) g_cnt[tile] = 0;   // reset for next graph replay
    }
}

// ---------------------------------------------------------------------------
// Inputs: 0 ally 1 enemy 2 wa1 3 ba1 4 wa2 5 ba2 6 we1 7 be1 8 we2 9 be2
// ---------------------------------------------------------------------------
extern "C" void kernel_launch(void* const* d_in, const int* in_sizes, int n_in,
                              void* d_out, int out_size) {
    const float* fa  = (const float*)d_in[0];
    const float* fe  = (const float*)d_in[1];
    const float* wa1 = (const float*)d_in[2];
    const float* ba1 = (const float*)d_in[3];
    const float* wa2 = (const float*)d_in[4];
    const float* ba2 = (const float*)d_in[5];
    const float* we1 = (const float*)d_in[6];
    const float* be1 = (const float*)d_in[7];
    const float* we2 = (const float*)d_in[8];
    const float* be2 = (const float*)d_in[9];
    float* out = (float*)d_out;

    cudaFuncSetAttribute(gemm_mma, cudaFuncAttributeMaxDynamicSharedMemorySize, SMEM_DYN);

    prep<<<BATCH + NPACK, 256>>>(fa, fe, wa1, ba1, wa2, ba2, we1, be1, we2, be2);
    gemm_mma<<<dim3(BATCH / 128, OUTD / 64, SPLIT), 256, SMEM_DYN>>>(out);
}